// round 15
// baseline (speedup 1.0000x reference)
#include <cuda_runtime.h>
#include <cuda_bf16.h>
#include <cstdint>

#define N_ROWS 4096
#define D_DIM  512
#define NUM_CL 512
#define MARGIN 0.3f

// ---------------- device scratch ----------------
__device__ float    g_sq[N_ROWS];
__device__ unsigned g_ap[N_ROWS];          // max intra-class dist^2 (bits)
__device__ unsigned g_an[N_ROWS];          // min inter-class dist^2 (bits)
__device__ float    g_cp[N_ROWS];
__device__ float    g_cn[N_ROWS];
__device__ float    g_csum[NUM_CL * D_DIM];
__device__ int      g_ccnt[NUM_CL];
__device__ float    g_tot[D_DIM];
__device__ float    g_cc;
__device__ int      g_ready[32];           // per-128-row-group prep completion
__device__ __align__(16) __nv_bfloat16 g_xb[N_ROWS * D_DIM];

// ---------------- helpers ----------------
__device__ __forceinline__ uint32_t smem_u32(const void* p) {
    uint32_t a;
    asm("{ .reg .u64 t; cvta.to.shared.u64 t, %1; cvt.u32.u64 %0, t; }" : "=r"(a) : "l"(p));
    return a;
}
__device__ __forceinline__ float blockReduceSum(float v, float* sh) {
    int tid = threadIdx.x;
    #pragma unroll
    for (int o = 16; o; o >>= 1) v += __shfl_down_sync(0xffffffffu, v, o);
    __syncthreads();
    if ((tid & 31) == 0) sh[tid >> 5] = v;
    __syncthreads();
    int nw = (blockDim.x + 31) >> 5;
    if (tid < 32) {
        v = (tid < nw) ? sh[tid] : 0.f;
        #pragma unroll
        for (int o = 16; o; o >>= 1) v += __shfl_down_sync(0xffffffffu, v, o);
    }
    return v;
}
__device__ __forceinline__ float warpReduceSum(float v) {
    #pragma unroll
    for (int o = 16; o; o >>= 1) v += __shfl_down_sync(0xffffffffu, v, o);
    return v;
}

// ---------------- prep: init + fp32->bf16 + squared norms (chain A) -------
__global__ void prep_kernel(const float* __restrict__ X) {
    __shared__ float sh[4];
    int r = blockIdx.x, t = threadIdx.x;   // 128 threads
    const float4 v = *(const float4*)&X[(size_t)r * D_DIM + t * 4];
    __nv_bfloat162 lo = __floats2bfloat162_rn(v.x, v.y);
    __nv_bfloat162 hi = __floats2bfloat162_rn(v.z, v.w);
    *(__nv_bfloat162*)&g_xb[(size_t)r * D_DIM + t * 4]     = lo;
    *(__nv_bfloat162*)&g_xb[(size_t)r * D_DIM + t * 4 + 2] = hi;
    float a = v.x * v.x + v.y * v.y + v.z * v.z + v.w * v.w;
    a = blockReduceSum(a, sh);
    if (t == 0) {
        g_sq[r] = a;
        g_ap[r] = 0u;
        g_an[r] = 0x7f800000u;
    }
    __syncthreads();                 // all block writes done
    if (t == 0) {
        __threadfence();             // make them device-visible
        atomicAdd(&g_ready[r >> 7], 1);
    }
}

// one block per class: bitmask membership scan (chain B head)
__global__ void __launch_bounds__(256)
classsum_kernel(const float* __restrict__ X, const int* __restrict__ T) {
    __shared__ unsigned mask[N_ROWS / 32];   // 128 words
    const int c = blockIdx.x, tid = threadIdx.x;

    if (c == 0 && tid == 0) g_cc = 0.f;      // cc accumulator init (chain B owns it)
    if (tid < N_ROWS / 32) mask[tid] = 0u;
    __syncthreads();
    {
        unsigned bits = 0u;
        const int r0 = tid * 16;
        #pragma unroll
        for (int i = 0; i < 16; i++)
            bits |= (T[r0 + i] == c) ? (1u << ((r0 + i) & 31)) : 0u;
        if (bits) atomicOr(&mask[r0 >> 5], bits);
    }
    __syncthreads();

    float a0 = 0.f, a1 = 0.f;
    int cnt = 0;
    #pragma unroll 4
    for (int w = 0; w < N_ROWS / 32; w++) {
        unsigned m = mask[w];
        while (m) {
            int b = __ffs(m) - 1;
            m &= m - 1;
            int r = w * 32 + b;
            cnt++;
            a0 += X[(size_t)r * D_DIM + tid];
            a1 += X[(size_t)r * D_DIM + tid + 256];
        }
    }
    g_csum[c * D_DIM + tid]       = a0;
    g_csum[c * D_DIM + tid + 256] = a1;
    if (tid == 0) g_ccnt[c] = cnt;
}

__global__ void tot_kernel() {   // grid 512, block 128
    __shared__ float sh[4];
    int d = blockIdx.x;
    float s = 0.f;
    for (int c = threadIdx.x; c < NUM_CL; c += 128) s += g_csum[c * D_DIM + d];
    s = blockReduceSum(s, sh);
    if (threadIdx.x == 0) g_tot[d] = s;
}

// ---------------- tensor-core (mma.sync) distance kernel ----------------
#define KC 64
#define STAGES (D_DIM / KC)      // 8
#define NSTG 3
#define STG_BYTES (128 * KC * 2) // 16384 per matrix per stage
#define NTILE 32                 // 4096/128

__device__ __forceinline__ void ldmx4(uint32_t& r0, uint32_t& r1, uint32_t& r2, uint32_t& r3,
                                      uint32_t addr) {
    asm volatile("ldmatrix.sync.aligned.m8n8.x4.shared.b16 {%0,%1,%2,%3}, [%4];"
                 : "=r"(r0), "=r"(r1), "=r"(r2), "=r"(r3) : "r"(addr));
}
__device__ __forceinline__ void mma_bf16(float* c, uint32_t a0, uint32_t a1, uint32_t a2,
                                         uint32_t a3, uint32_t b0, uint32_t b1) {
    asm volatile("mma.sync.aligned.m16n8k16.row.col.f32.bf16.bf16.f32 "
                 "{%0,%1,%2,%3}, {%4,%5,%6,%7}, {%8,%9}, {%0,%1,%2,%3};"
                 : "+f"(c[0]), "+f"(c[1]), "+f"(c[2]), "+f"(c[3])
                 : "r"(a0), "r"(a1), "r"(a2), "r"(a3), "r"(b0), "r"(b1));
}
#define CP16(dst, src) \
    asm volatile("cp.async.cg.shared.global [%0], [%1], 16;" :: "r"(dst), "l"(src))
#define CP_COMMIT() asm volatile("cp.async.commit_group;" ::: "memory")

__global__ void __launch_bounds__(256, 2)
dist_mma_kernel(const int* __restrict__ T) {
    extern __shared__ __align__(1024) unsigned char dsm[];   // NSTG*2*16KB = 96KB
    __shared__ float sqRs[128], sqCs[128];
    __shared__ int   tRs[128], tCs[128];
    __shared__ unsigned apS[128], anS[128], apSc[128], anSc[128];

    // triangular decode: tile t -> (by, bx), bx >= by
    const int t = blockIdx.x;
    int by = (int)((2.f * NTILE + 1.f - sqrtf((2.f * NTILE + 1.f) * (2.f * NTILE + 1.f)
                                              - 8.f * (float)t)) * 0.5f);
    while (by > 0 && (by * NTILE - (by * (by - 1)) / 2) > t) by--;
    while (((by + 1) * NTILE - ((by + 1) * by) / 2) <= t) by++;
    const int bx = by + (t - (by * NTILE - (by * (by - 1)) / 2));

    const int tid = threadIdx.x, wid = tid >> 5, lane = tid & 31;
    const int rowBase = by * 128;
    const int colBase = bx * 128;
    const int warpM = (wid >> 2) * 64;
    const int warpN = (wid & 3) * 32;

    if (tid < 128) {
        apS[tid] = 0u;  anS[tid] = 0x7f800000u;
        apSc[tid] = 0u; anSc[tid] = 0x7f800000u;
    }

    const uint32_t sbA = smem_u32(dsm);
    const uint32_t sbB = sbA + NSTG * STG_BYTES;
    const char* Xb = (const char*)g_xb;

    const int lr = tid >> 3, lu = tid & 7;
    const uint32_t so0 = (uint32_t)(lr * 128 + ((lu * 16) ^ ((lr & 7) << 4)));
    const char* gA0 = Xb + ((size_t)(rowBase + lr) * D_DIM + lu * 8) * 2;
    const char* gB0 = Xb + ((size_t)(colBase + lr) * D_DIM + lu * 8) * 2;

    const int aRow  = warpM + (lane & 15);
    const int aKH   = (lane >> 4) * 16;
    const uint32_t aXor = ((unsigned)(aRow & 7)) << 4;
    const int nRow  = warpN + (lane & 7) + ((lane >> 4) << 3);
    const int bKH   = ((lane >> 3) & 1) * 16;
    const uint32_t bXor = ((unsigned)(nRow & 7)) << 4;

    float acc[4][4][4];
    #pragma unroll
    for (int i = 0; i < 4; i++)
        #pragma unroll
        for (int j = 0; j < 4; j++)
            #pragma unroll
            for (int c = 0; c < 4; c++) acc[i][j][c] = 0.f;

    // ---- fine-grained wait: only THIS tile's row/col groups of prep ----
    // (PDL launch lets us start while prep is still draining; prep's grid is
    //  fully dispatched before any dist CTA, so spinning cannot starve it.)
    if (tid == 0) {
        volatile int* rdy = g_ready;
        while (rdy[by] != 128) { }
        while (rdy[bx] != 128) { }
    }
    __syncthreads();
    __threadfence();   // acquire: order flag read before data reads

    if (tid < 128) {
        sqRs[tid] = g_sq[rowBase + tid];
        sqCs[tid] = g_sq[colBase + tid];
        tRs[tid]  = T[rowBase + tid];
        tCs[tid]  = T[colBase + tid];
    }

    #define ISSUE_STAGE(s_) do { \
        const uint32_t bo_ = (uint32_t)(((s_) % NSTG) * STG_BYTES) + so0; \
        const size_t ko_ = (size_t)(s_) * (KC * 2); \
        CP16(sbA + bo_,          gA0 + ko_); \
        CP16(sbA + bo_ + 4096,   gA0 + ko_ + 32768); \
        CP16(sbA + bo_ + 8192,   gA0 + ko_ + 65536); \
        CP16(sbA + bo_ + 12288,  gA0 + ko_ + 98304); \
        CP16(sbB + bo_,          gB0 + ko_); \
        CP16(sbB + bo_ + 4096,   gB0 + ko_ + 32768); \
        CP16(sbB + bo_ + 8192,   gB0 + ko_ + 65536); \
        CP16(sbB + bo_ + 12288,  gB0 + ko_ + 98304); \
        CP_COMMIT(); \
    } while (0)

    ISSUE_STAGE(0);
    ISSUE_STAGE(1);

    #pragma unroll
    for (int s = 0; s < STAGES; s++) {
        if (s < STAGES - 1) asm volatile("cp.async.wait_group 1;" ::: "memory");
        else                asm volatile("cp.async.wait_group 0;" ::: "memory");
        __syncthreads();
        if (s + 2 < STAGES) ISSUE_STAGE(s + 2);

        const uint32_t bufOff = (uint32_t)((s % NSTG) * STG_BYTES);
        #pragma unroll
        for (int ks = 0; ks < 4; ks++) {
            uint32_t b[4][2];
            #pragma unroll
            for (int nb = 0; nb < 2; nb++) {
                uint32_t addr = sbB + bufOff + (uint32_t)((nRow + nb * 16) * 128)
                              + (uint32_t)((ks * 32 + bKH) ^ bXor);
                uint32_t q0, q1, q2, q3;
                ldmx4(q0, q1, q2, q3, addr);
                b[nb * 2][0] = q0; b[nb * 2][1] = q1;
                b[nb * 2 + 1][0] = q2; b[nb * 2 + 1][1] = q3;
            }
            #pragma unroll
            for (int mi = 0; mi < 4; mi++) {
                uint32_t addr = sbA + bufOff + (uint32_t)((aRow + mi * 16) * 128)
                              + (uint32_t)((ks * 32 + aKH) ^ aXor);
                uint32_t a0, a1, a2, a3;
                ldmx4(a0, a1, a2, a3, addr);
                #pragma unroll
                for (int nj = 0; nj < 4; nj++)
                    mma_bf16(acc[mi][nj], a0, a1, a2, a3, b[nj][0], b[nj][1]);
            }
        }
    }

    // ---- epilogue ----
    const int g = lane >> 2, q = lane & 3;
    const float INF = __int_as_float(0x7f800000);

    #pragma unroll
    for (int mi = 0; mi < 4; mi++) {
        #pragma unroll
        for (int half = 0; half < 2; half++) {
            const int row = warpM + mi * 16 + g + half * 8;
            const float sqi = sqRs[row];
            const int   ti  = tRs[row];
            float ap = 0.f, an = INF;
            #pragma unroll
            for (int nj = 0; nj < 4; nj++) {
                #pragma unroll
                for (int c = 0; c < 2; c++) {
                    const int col = warpN + nj * 8 + q * 2 + c;
                    float d2 = fmaxf(sqi + sqCs[col] - 2.f * acc[mi][nj][half * 2 + c], 1e-12f);
                    acc[mi][nj][half * 2 + c] = d2;
                    if (ti == tCs[col]) ap = fmaxf(ap, d2);
                    else                an = fminf(an, d2);
                }
            }
            ap = fmaxf(ap, __shfl_xor_sync(0xffffffffu, ap, 1));
            ap = fmaxf(ap, __shfl_xor_sync(0xffffffffu, ap, 2));
            an = fminf(an, __shfl_xor_sync(0xffffffffu, an, 1));
            an = fminf(an, __shfl_xor_sync(0xffffffffu, an, 2));
            if (q == 0) {
                atomicMax(&apS[row], __float_as_uint(ap));
                atomicMin(&anS[row], __float_as_uint(an));
            }
        }
    }
    if (bx != by) {   // diagonal tiles: column pass duplicates row pass
        #pragma unroll
        for (int nj = 0; nj < 4; nj++) {
            #pragma unroll
            for (int c = 0; c < 2; c++) {
                const int col = warpN + nj * 8 + q * 2 + c;
                const int tc = tCs[col];
                float ap = 0.f, an = INF;
                #pragma unroll
                for (int mi = 0; mi < 4; mi++) {
                    #pragma unroll
                    for (int half = 0; half < 2; half++) {
                        const int row = warpM + mi * 16 + g + half * 8;
                        float d2 = acc[mi][nj][half * 2 + c];
                        if (tRs[row] == tc) ap = fmaxf(ap, d2);
                        else                an = fminf(an, d2);
                    }
                }
                ap = fmaxf(ap, __shfl_xor_sync(0xffffffffu, ap, 4));
                ap = fmaxf(ap, __shfl_xor_sync(0xffffffffu, ap, 8));
                ap = fmaxf(ap, __shfl_xor_sync(0xffffffffu, ap, 16));
                an = fminf(an, __shfl_xor_sync(0xffffffffu, an, 4));
                an = fminf(an, __shfl_xor_sync(0xffffffffu, an, 8));
                an = fminf(an, __shfl_xor_sync(0xffffffffu, an, 16));
                if (g == 0) {
                    atomicMax(&apSc[col], __float_as_uint(ap));
                    atomicMin(&anSc[col], __float_as_uint(an));
                }
            }
        }
    }
    __syncthreads();
    if (tid < 128) {
        atomicMax(&g_ap[rowBase + tid], apS[tid]);
        atomicMin(&g_an[rowBase + tid], anS[tid]);
        if (bx != by) {
            atomicMax(&g_ap[colBase + tid], apSc[tid]);
            atomicMin(&g_an[colBase + tid], anSc[tid]);
        }
    }
}

// ---------------- centroid (+ fused cc): warp per row ----------------
__global__ void __launch_bounds__(256)
centroid_kernel(const float* __restrict__ X, const int* __restrict__ T) {
    const int warp = threadIdx.x >> 5, lane = threadIdx.x & 31;
    const int i = blockIdx.x * 8 + warp;           // row; grid = 512
    const int c = T[i];
    const float cnt  = (float)g_ccnt[c];
    const float inv1 = 1.f / cnt;
    const float inv2 = 1.f / ((float)N_ROWS - cnt);

    float a1 = 0.f, a2 = 0.f;
    #pragma unroll
    for (int it = 0; it < 4; it++) {
        const int d = (lane + it * 32) * 4;
        const float4 cs = *(const float4*)&g_csum[c * D_DIM + d];
        const float4 x  = *(const float4*)&X[(size_t)i * D_DIM + d];
        const float4 tt = *(const float4*)&g_tot[d];
        float icx = cs.x * inv1 - x.x, icy = cs.y * inv1 - x.y;
        float icz = cs.z * inv1 - x.z, icw = cs.w * inv1 - x.w;
        a1 += icx * icx + icy * icy + icz * icz + icw * icw;
        float ocx = (tt.x - cs.x) * inv2 - x.x, ocy = (tt.y - cs.y) * inv2 - x.y;
        float ocz = (tt.z - cs.z) * inv2 - x.z, ocw = (tt.w - cs.w) * inv2 - x.w;
        a2 += ocx * ocx + ocy * ocy + ocz * ocz + ocw * ocw;
    }
    a1 = warpReduceSum(a1);
    a2 = warpReduceSum(a2);
    if (lane == 0) { g_cp[i] = sqrtf(a1); g_cn[i] = sqrtf(a2); }

    // fused cc: warps owning rows 0..NUM_CL-1 also handle class = row index
    if (i < NUM_CL) {
        const int cnt2 = g_ccnt[i];
        if (cnt2 > 0) {
            const float fc = (float)cnt2;
            const float j1 = 1.f / fc;
            const float j2 = 1.f / ((float)N_ROWS - fc);
            float a = 0.f;
            #pragma unroll
            for (int it = 0; it < 4; it++) {
                const int d = (lane + it * 32) * 4;
                const float4 cs = *(const float4*)&g_csum[i * D_DIM + d];
                const float4 tt = *(const float4*)&g_tot[d];
                float dx = cs.x * j1 - (tt.x - cs.x) * j2;
                float dy = cs.y * j1 - (tt.y - cs.y) * j2;
                float dz = cs.z * j1 - (tt.z - cs.z) * j2;
                float dw = cs.w * j1 - (tt.w - cs.w) * j2;
                a += dx * dx + dy * dy + dz * dz + dw * dw;
            }
            a = warpReduceSum(a);
            if (lane == 0) atomicAdd(&g_cc, fc * sqrtf(a));
        }
    }
}

__global__ void final_kernel(float* __restrict__ out) {
    __shared__ float sh[8];
    float s1 = 0.f, s2 = 0.f;
    for (int i = threadIdx.x; i < N_ROWS; i += 256) {
        float ap = sqrtf(__uint_as_float(g_ap[i]));
        float an = sqrtf(__uint_as_float(g_an[i]));
        s1 += fmaxf(ap - an + MARGIN, 0.f);
        s2 += fmaxf(g_cp[i] - g_cn[i] + MARGIN, 0.f);
    }
    s1 = blockReduceSum(s1, sh);
    __syncthreads();
    s2 = blockReduceSum(s2, sh);
    if (threadIdx.x == 0) {
        out[0] = s1 / (float)N_ROWS;
        out[1] = s2 / (float)N_ROWS;
        out[2] = -g_cc / (float)N_ROWS;
    }
    if (threadIdx.x < 32) g_ready[threadIdx.x] = 0;   // reset for next call/replay
}

// ---------------- entry ----------------
extern "C" void kernel_launch(void* const* d_in, const int* in_sizes, int n_in,
                              void* d_out, int out_size) {
    const float* X = (const float*)d_in[0];
    const int*   T = (const int*)d_in[1];
    float* out = (float*)d_out;

    cudaFuncSetAttribute(dist_mma_kernel,
                         cudaFuncAttributeMaxDynamicSharedMemorySize,
                         NSTG * 2 * STG_BYTES);

    cudaStream_t s2;
    cudaStreamCreateWithFlags(&s2, cudaStreamNonBlocking);
    cudaEvent_t eFork, eJoin;
    cudaEventCreateWithFlags(&eFork, cudaEventDisableTiming);
    cudaEventCreateWithFlags(&eJoin, cudaEventDisableTiming);

    // fork
    cudaEventRecord(eFork, 0);
    cudaStreamWaitEvent(s2, eFork, 0);

    // chain A head (origin stream)
    prep_kernel<<<N_ROWS, 128>>>(X);                       // issue 0

    // chain B (side stream)
    classsum_kernel<<<NUM_CL, 256, 0, s2>>>(X, T);         // issue 1
    tot_kernel<<<D_DIM, 128, 0, s2>>>();                   // issue 2

    // dist at issue index 3. PDL attribute allows launch overlap with prep's
    // tail; correctness is enforced by the per-row-group g_ready flags inside.
    {
        cudaLaunchConfig_t cfg = {};
        cfg.gridDim = dim3((unsigned)(NTILE * (NTILE + 1) / 2), 1, 1);  // 528
        cfg.blockDim = dim3(256, 1, 1);
        cfg.dynamicSmemBytes = NSTG * 2 * STG_BYTES;
        cfg.stream = 0;
        cudaLaunchAttribute attrs[1];
        attrs[0].id = cudaLaunchAttributeProgrammaticStreamSerialization;
        attrs[0].val.programmaticStreamSerializationAllowed = 1;
        cfg.attrs = attrs;
        cfg.numAttrs = 1;
        cudaLaunchKernelEx(&cfg, dist_mma_kernel, T);      // issue 3
    }

    // chain B tail
    centroid_kernel<<<N_ROWS / 8, 256, 0, s2>>>(X, T);     // issue 4
    cudaEventRecord(eJoin, s2);

    // join, then final reduction (also resets g_ready for the next replay)
    cudaStreamWaitEvent(0, eJoin, 0);
    final_kernel<<<1, 256>>>(out);                         // issue 5
}

// round 16
// speedup vs baseline: 1.0240x; 1.0240x over previous
#include <cuda_runtime.h>
#include <cuda_bf16.h>
#include <cstdint>

#define N_ROWS 4096
#define D_DIM  512
#define NUM_CL 512
#define MARGIN 0.3f

// ---------------- device scratch ----------------
__device__ float    g_sq[N_ROWS];
__device__ unsigned g_ap[N_ROWS];          // max intra-class dist^2 (bits)
__device__ unsigned g_an[N_ROWS];          // min inter-class dist^2 (bits)
__device__ float    g_cp[N_ROWS];
__device__ float    g_cn[N_ROWS];
__device__ float    g_csum[NUM_CL * D_DIM];
__device__ int      g_ccnt[NUM_CL];
__device__ float    g_tot[D_DIM];
__device__ float    g_cc;
__device__ __align__(16) __nv_bfloat16 g_xb[N_ROWS * D_DIM];

// ---------------- helpers ----------------
__device__ __forceinline__ uint32_t smem_u32(const void* p) {
    uint32_t a;
    asm("{ .reg .u64 t; cvta.to.shared.u64 t, %1; cvt.u32.u64 %0, t; }" : "=r"(a) : "l"(p));
    return a;
}
__device__ __forceinline__ float blockReduceSum(float v, float* sh) {
    int tid = threadIdx.x;
    #pragma unroll
    for (int o = 16; o; o >>= 1) v += __shfl_down_sync(0xffffffffu, v, o);
    __syncthreads();
    if ((tid & 31) == 0) sh[tid >> 5] = v;
    __syncthreads();
    int nw = (blockDim.x + 31) >> 5;
    if (tid < 32) {
        v = (tid < nw) ? sh[tid] : 0.f;
        #pragma unroll
        for (int o = 16; o; o >>= 1) v += __shfl_down_sync(0xffffffffu, v, o);
    }
    return v;
}
__device__ __forceinline__ float warpReduceSum(float v) {
    #pragma unroll
    for (int o = 16; o; o >>= 1) v += __shfl_down_sync(0xffffffffu, v, o);
    return v;
}

// ---------------- prep: init + fp32->bf16 + squared norms (chain A) -------
__global__ void prep_kernel(const float* __restrict__ X) {
    __shared__ float sh[4];
    int r = blockIdx.x, t = threadIdx.x;   // 128 threads
    const float4 v = *(const float4*)&X[(size_t)r * D_DIM + t * 4];
    __nv_bfloat162 lo = __floats2bfloat162_rn(v.x, v.y);
    __nv_bfloat162 hi = __floats2bfloat162_rn(v.z, v.w);
    *(__nv_bfloat162*)&g_xb[(size_t)r * D_DIM + t * 4]     = lo;
    *(__nv_bfloat162*)&g_xb[(size_t)r * D_DIM + t * 4 + 2] = hi;
    float a = v.x * v.x + v.y * v.y + v.z * v.z + v.w * v.w;
    a = blockReduceSum(a, sh);
    if (t == 0) {
        g_sq[r] = a;
        g_ap[r] = 0u;
        g_an[r] = 0x7f800000u;
    }
}

// one block per class: bitmask membership scan (chain B head)
__global__ void __launch_bounds__(256)
classsum_kernel(const float* __restrict__ X, const int* __restrict__ T) {
    __shared__ unsigned mask[N_ROWS / 32];   // 128 words
    const int c = blockIdx.x, tid = threadIdx.x;

    if (c == 0 && tid == 0) g_cc = 0.f;      // cc accumulator init (chain B owns it)
    if (tid < N_ROWS / 32) mask[tid] = 0u;
    __syncthreads();
    {
        unsigned bits = 0u;
        const int r0 = tid * 16;
        #pragma unroll
        for (int i = 0; i < 16; i++)
            bits |= (T[r0 + i] == c) ? (1u << ((r0 + i) & 31)) : 0u;
        if (bits) atomicOr(&mask[r0 >> 5], bits);
    }
    __syncthreads();

    float a0 = 0.f, a1 = 0.f;
    int cnt = 0;
    #pragma unroll 4
    for (int w = 0; w < N_ROWS / 32; w++) {
        unsigned m = mask[w];
        while (m) {
            int b = __ffs(m) - 1;
            m &= m - 1;
            int r = w * 32 + b;
            cnt++;
            a0 += X[(size_t)r * D_DIM + tid];
            a1 += X[(size_t)r * D_DIM + tid + 256];
        }
    }
    g_csum[c * D_DIM + tid]       = a0;
    g_csum[c * D_DIM + tid + 256] = a1;
    if (tid == 0) g_ccnt[c] = cnt;
}

__global__ void tot_kernel() {   // grid 512, block 128
    __shared__ float sh[4];
    int d = blockIdx.x;
    float s = 0.f;
    for (int c = threadIdx.x; c < NUM_CL; c += 128) s += g_csum[c * D_DIM + d];
    s = blockReduceSum(s, sh);
    if (threadIdx.x == 0) g_tot[d] = s;
}

// ---------------- tensor-core (mma.sync) distance kernel ----------------
#define KC 64
#define STAGES (D_DIM / KC)      // 8
#define NSTG 3
#define STG_BYTES (128 * KC * 2) // 16384 per matrix per stage
#define NTILE 32                 // 4096/128

__device__ __forceinline__ void ldmx4(uint32_t& r0, uint32_t& r1, uint32_t& r2, uint32_t& r3,
                                      uint32_t addr) {
    asm volatile("ldmatrix.sync.aligned.m8n8.x4.shared.b16 {%0,%1,%2,%3}, [%4];"
                 : "=r"(r0), "=r"(r1), "=r"(r2), "=r"(r3) : "r"(addr));
}
__device__ __forceinline__ void mma_bf16(float* c, uint32_t a0, uint32_t a1, uint32_t a2,
                                         uint32_t a3, uint32_t b0, uint32_t b1) {
    asm volatile("mma.sync.aligned.m16n8k16.row.col.f32.bf16.bf16.f32 "
                 "{%0,%1,%2,%3}, {%4,%5,%6,%7}, {%8,%9}, {%0,%1,%2,%3};"
                 : "+f"(c[0]), "+f"(c[1]), "+f"(c[2]), "+f"(c[3])
                 : "r"(a0), "r"(a1), "r"(a2), "r"(a3), "r"(b0), "r"(b1));
}
#define CP16(dst, src) \
    asm volatile("cp.async.cg.shared.global [%0], [%1], 16;" :: "r"(dst), "l"(src))
#define CP_COMMIT() asm volatile("cp.async.commit_group;" ::: "memory")

__global__ void __launch_bounds__(256, 2)
dist_mma_kernel(const int* __restrict__ T) {
    extern __shared__ __align__(1024) unsigned char dsm[];   // NSTG*2*16KB = 96KB
    __shared__ float sqRs[128], sqCs[128];
    __shared__ int   tRs[128], tCs[128];
    __shared__ unsigned apS[128], anS[128], apSc[128], anSc[128];

    // ---- pre-PDL-wait setup: no global reads of prep outputs here ----
    const int t = blockIdx.x;
    int by = (int)((2.f * NTILE + 1.f - sqrtf((2.f * NTILE + 1.f) * (2.f * NTILE + 1.f)
                                              - 8.f * (float)t)) * 0.5f);
    while (by > 0 && (by * NTILE - (by * (by - 1)) / 2) > t) by--;
    while (((by + 1) * NTILE - ((by + 1) * by) / 2) <= t) by++;
    const int bx = by + (t - (by * NTILE - (by * (by - 1)) / 2));

    const int tid = threadIdx.x, wid = tid >> 5, lane = tid & 31;
    const int rowBase = by * 128;
    const int colBase = bx * 128;
    const int warpM = (wid >> 2) * 64;
    const int warpN = (wid & 3) * 32;

    if (tid < 128) {
        apS[tid] = 0u;  anS[tid] = 0x7f800000u;
        apSc[tid] = 0u; anSc[tid] = 0x7f800000u;
    }

    const uint32_t sbA = smem_u32(dsm);
    const uint32_t sbB = sbA + NSTG * STG_BYTES;
    const char* Xb = (const char*)g_xb;

    // loader bases: chunk it adds +4096 smem / +32768 gmem (constant strides)
    const int lr = tid >> 3, lu = tid & 7;
    const uint32_t so0 = (uint32_t)(lr * 128 + ((lu * 16) ^ ((lr & 7) << 4)));
    const char* gA0 = Xb + ((size_t)(rowBase + lr) * D_DIM + lu * 8) * 2;
    const char* gB0 = Xb + ((size_t)(colBase + lr) * D_DIM + lu * 8) * 2;

    const int aRow  = warpM + (lane & 15);
    const int aKH   = (lane >> 4) * 16;
    const uint32_t aXor = ((unsigned)(aRow & 7)) << 4;
    const int nRow  = warpN + (lane & 7) + ((lane >> 4) << 3);
    const int bKH   = ((lane >> 3) & 1) * 16;
    const uint32_t bXor = ((unsigned)(nRow & 7)) << 4;

    float acc[4][4][4];
    #pragma unroll
    for (int i = 0; i < 4; i++)
        #pragma unroll
        for (int j = 0; j < 4; j++)
            #pragma unroll
            for (int c = 0; c < 4; c++) acc[i][j][c] = 0.f;

    // ---- PDL: wait for prep's writes to be visible ----
    asm volatile("griddepcontrol.wait;" ::: "memory");

    if (tid < 128) {
        sqRs[tid] = g_sq[rowBase + tid];
        sqCs[tid] = g_sq[colBase + tid];
        tRs[tid]  = T[rowBase + tid];
        tCs[tid]  = T[colBase + tid];
    }

    #define ISSUE_STAGE(s_) do { \
        const uint32_t bo_ = (uint32_t)(((s_) % NSTG) * STG_BYTES) + so0; \
        const size_t ko_ = (size_t)(s_) * (KC * 2); \
        CP16(sbA + bo_,          gA0 + ko_); \
        CP16(sbA + bo_ + 4096,   gA0 + ko_ + 32768); \
        CP16(sbA + bo_ + 8192,   gA0 + ko_ + 65536); \
        CP16(sbA + bo_ + 12288,  gA0 + ko_ + 98304); \
        CP16(sbB + bo_,          gB0 + ko_); \
        CP16(sbB + bo_ + 4096,   gB0 + ko_ + 32768); \
        CP16(sbB + bo_ + 8192,   gB0 + ko_ + 65536); \
        CP16(sbB + bo_ + 12288,  gB0 + ko_ + 98304); \
        CP_COMMIT(); \
    } while (0)

    ISSUE_STAGE(0);
    ISSUE_STAGE(1);

    #pragma unroll
    for (int s = 0; s < STAGES; s++) {
        if (s < STAGES - 1) asm volatile("cp.async.wait_group 1;" ::: "memory");
        else                asm volatile("cp.async.wait_group 0;" ::: "memory");
        __syncthreads();
        if (s + 2 < STAGES) ISSUE_STAGE(s + 2);

        const uint32_t bufOff = (uint32_t)((s % NSTG) * STG_BYTES);
        #pragma unroll
        for (int ks = 0; ks < 4; ks++) {
            uint32_t b[4][2];
            #pragma unroll
            for (int nb = 0; nb < 2; nb++) {
                uint32_t addr = sbB + bufOff + (uint32_t)((nRow + nb * 16) * 128)
                              + (uint32_t)((ks * 32 + bKH) ^ bXor);
                uint32_t q0, q1, q2, q3;
                ldmx4(q0, q1, q2, q3, addr);
                b[nb * 2][0] = q0; b[nb * 2][1] = q1;
                b[nb * 2 + 1][0] = q2; b[nb * 2 + 1][1] = q3;
            }
            #pragma unroll
            for (int mi = 0; mi < 4; mi++) {
                uint32_t addr = sbA + bufOff + (uint32_t)((aRow + mi * 16) * 128)
                              + (uint32_t)((ks * 32 + aKH) ^ aXor);
                uint32_t a0, a1, a2, a3;
                ldmx4(a0, a1, a2, a3, addr);
                #pragma unroll
                for (int nj = 0; nj < 4; nj++)
                    mma_bf16(acc[mi][nj], a0, a1, a2, a3, b[nj][0], b[nj][1]);
            }
        }
    }

    // ---- epilogue ----
    const int g = lane >> 2, q = lane & 3;
    const float INF = __int_as_float(0x7f800000);

    #pragma unroll
    for (int mi = 0; mi < 4; mi++) {
        #pragma unroll
        for (int half = 0; half < 2; half++) {
            const int row = warpM + mi * 16 + g + half * 8;
            const float sqi = sqRs[row];
            const int   ti  = tRs[row];
            float ap = 0.f, an = INF;
            #pragma unroll
            for (int nj = 0; nj < 4; nj++) {
                #pragma unroll
                for (int c = 0; c < 2; c++) {
                    const int col = warpN + nj * 8 + q * 2 + c;
                    float d2 = fmaxf(sqi + sqCs[col] - 2.f * acc[mi][nj][half * 2 + c], 1e-12f);
                    acc[mi][nj][half * 2 + c] = d2;
                    if (ti == tCs[col]) ap = fmaxf(ap, d2);
                    else                an = fminf(an, d2);
                }
            }
            ap = fmaxf(ap, __shfl_xor_sync(0xffffffffu, ap, 1));
            ap = fmaxf(ap, __shfl_xor_sync(0xffffffffu, ap, 2));
            an = fminf(an, __shfl_xor_sync(0xffffffffu, an, 1));
            an = fminf(an, __shfl_xor_sync(0xffffffffu, an, 2));
            if (q == 0) {
                atomicMax(&apS[row], __float_as_uint(ap));
                atomicMin(&anS[row], __float_as_uint(an));
            }
        }
    }
    if (bx != by) {   // diagonal tiles: column pass duplicates row pass
        #pragma unroll
        for (int nj = 0; nj < 4; nj++) {
            #pragma unroll
            for (int c = 0; c < 2; c++) {
                const int col = warpN + nj * 8 + q * 2 + c;
                const int tc = tCs[col];
                float ap = 0.f, an = INF;
                #pragma unroll
                for (int mi = 0; mi < 4; mi++) {
                    #pragma unroll
                    for (int half = 0; half < 2; half++) {
                        const int row = warpM + mi * 16 + g + half * 8;
                        float d2 = acc[mi][nj][half * 2 + c];
                        if (tRs[row] == tc) ap = fmaxf(ap, d2);
                        else                an = fminf(an, d2);
                    }
                }
                ap = fmaxf(ap, __shfl_xor_sync(0xffffffffu, ap, 4));
                ap = fmaxf(ap, __shfl_xor_sync(0xffffffffu, ap, 8));
                ap = fmaxf(ap, __shfl_xor_sync(0xffffffffu, ap, 16));
                an = fminf(an, __shfl_xor_sync(0xffffffffu, an, 4));
                an = fminf(an, __shfl_xor_sync(0xffffffffu, an, 8));
                an = fminf(an, __shfl_xor_sync(0xffffffffu, an, 16));
                if (g == 0) {
                    atomicMax(&apSc[col], __float_as_uint(ap));
                    atomicMin(&anSc[col], __float_as_uint(an));
                }
            }
        }
    }
    __syncthreads();
    if (tid < 128) {
        atomicMax(&g_ap[rowBase + tid], apS[tid]);
        atomicMin(&g_an[rowBase + tid], anS[tid]);
        if (bx != by) {
            atomicMax(&g_ap[colBase + tid], apSc[tid]);
            atomicMin(&g_an[colBase + tid], anSc[tid]);
        }
    }
}

// ---------------- centroid (+ fused cc): warp per row ----------------
__global__ void __launch_bounds__(256)
centroid_kernel(const float* __restrict__ X, const int* __restrict__ T) {
    const int warp = threadIdx.x >> 5, lane = threadIdx.x & 31;
    const int i = blockIdx.x * 8 + warp;           // row; grid = 512
    const int c = T[i];
    const float cnt  = (float)g_ccnt[c];
    const float inv1 = 1.f / cnt;
    const float inv2 = 1.f / ((float)N_ROWS - cnt);

    float a1 = 0.f, a2 = 0.f;
    #pragma unroll
    for (int it = 0; it < 4; it++) {
        const int d = (lane + it * 32) * 4;
        const float4 cs = *(const float4*)&g_csum[c * D_DIM + d];
        const float4 x  = *(const float4*)&X[(size_t)i * D_DIM + d];
        const float4 tt = *(const float4*)&g_tot[d];
        float icx = cs.x * inv1 - x.x, icy = cs.y * inv1 - x.y;
        float icz = cs.z * inv1 - x.z, icw = cs.w * inv1 - x.w;
        a1 += icx * icx + icy * icy + icz * icz + icw * icw;
        float ocx = (tt.x - cs.x) * inv2 - x.x, ocy = (tt.y - cs.y) * inv2 - x.y;
        float ocz = (tt.z - cs.z) * inv2 - x.z, ocw = (tt.w - cs.w) * inv2 - x.w;
        a2 += ocx * ocx + ocy * ocy + ocz * ocz + ocw * ocw;
    }
    a1 = warpReduceSum(a1);
    a2 = warpReduceSum(a2);
    if (lane == 0) { g_cp[i] = sqrtf(a1); g_cn[i] = sqrtf(a2); }

    // fused cc: warps owning rows 0..NUM_CL-1 also handle class = row index
    if (i < NUM_CL) {
        const int cnt2 = g_ccnt[i];
        if (cnt2 > 0) {
            const float fc = (float)cnt2;
            const float j1 = 1.f / fc;
            const float j2 = 1.f / ((float)N_ROWS - fc);
            float a = 0.f;
            #pragma unroll
            for (int it = 0; it < 4; it++) {
                const int d = (lane + it * 32) * 4;
                const float4 cs = *(const float4*)&g_csum[i * D_DIM + d];
                const float4 tt = *(const float4*)&g_tot[d];
                float dx = cs.x * j1 - (tt.x - cs.x) * j2;
                float dy = cs.y * j1 - (tt.y - cs.y) * j2;
                float dz = cs.z * j1 - (tt.z - cs.z) * j2;
                float dw = cs.w * j1 - (tt.w - cs.w) * j2;
                a += dx * dx + dy * dy + dz * dz + dw * dw;
            }
            a = warpReduceSum(a);
            if (lane == 0) atomicAdd(&g_cc, fc * sqrtf(a));
        }
    }
}

__global__ void final_kernel(float* __restrict__ out) {
    __shared__ float sh[8];
    float s1 = 0.f, s2 = 0.f;
    for (int i = threadIdx.x; i < N_ROWS; i += 256) {
        float ap = sqrtf(__uint_as_float(g_ap[i]));
        float an = sqrtf(__uint_as_float(g_an[i]));
        s1 += fmaxf(ap - an + MARGIN, 0.f);
        s2 += fmaxf(g_cp[i] - g_cn[i] + MARGIN, 0.f);
    }
    s1 = blockReduceSum(s1, sh);
    __syncthreads();
    s2 = blockReduceSum(s2, sh);
    if (threadIdx.x == 0) {
        out[0] = s1 / (float)N_ROWS;
        out[1] = s2 / (float)N_ROWS;
        out[2] = -g_cc / (float)N_ROWS;
    }
}

// ---------------- entry ----------------
extern "C" void kernel_launch(void* const* d_in, const int* in_sizes, int n_in,
                              void* d_out, int out_size) {
    const float* X = (const float*)d_in[0];
    const int*   T = (const int*)d_in[1];
    float* out = (float*)d_out;

    cudaFuncSetAttribute(dist_mma_kernel,
                         cudaFuncAttributeMaxDynamicSharedMemorySize,
                         NSTG * 2 * STG_BYTES);

    cudaStream_t s2;
    cudaStreamCreateWithFlags(&s2, cudaStreamNonBlocking);
    cudaEvent_t eFork, eJoin;
    cudaEventCreateWithFlags(&eFork, cudaEventDisableTiming);
    cudaEventCreateWithFlags(&eJoin, cudaEventDisableTiming);

    // fork
    cudaEventRecord(eFork, 0);
    cudaStreamWaitEvent(s2, eFork, 0);

    // chain A head (origin stream)
    prep_kernel<<<N_ROWS, 128>>>(X);                       // issue 0

    // chain B (side stream)
    classsum_kernel<<<NUM_CL, 256, 0, s2>>>(X, T);         // issue 1
    tot_kernel<<<D_DIM, 128, 0, s2>>>();                   // issue 2

    // dist at issue index 3. PDL w.r.t. prep (same stream).
    {
        cudaLaunchConfig_t cfg = {};
        cfg.gridDim = dim3((unsigned)(NTILE * (NTILE + 1) / 2), 1, 1);  // 528
        cfg.blockDim = dim3(256, 1, 1);
        cfg.dynamicSmemBytes = NSTG * 2 * STG_BYTES;
        cfg.stream = 0;
        cudaLaunchAttribute attrs[1];
        attrs[0].id = cudaLaunchAttributeProgrammaticStreamSerialization;
        attrs[0].val.programmaticStreamSerializationAllowed = 1;
        cfg.attrs = attrs;
        cfg.numAttrs = 1;
        cudaLaunchKernelEx(&cfg, dist_mma_kernel, T);      // issue 3
    }

    // chain B tail
    centroid_kernel<<<N_ROWS / 8, 256, 0, s2>>>(X, T);     // issue 4
    cudaEventRecord(eJoin, s2);

    // join, then final reduction
    cudaStreamWaitEvent(0, eJoin, 0);
    final_kernel<<<1, 256>>>(out);                         // issue 5
}

// round 17
// speedup vs baseline: 1.0601x; 1.0352x over previous
#include <cuda_runtime.h>
#include <cuda_bf16.h>
#include <cstdint>

#define N_ROWS 4096
#define D_DIM  512
#define NUM_CL 512
#define MARGIN 0.3f
#define ARRIVALS (528 + 512)     // dist CTAs + centroid CTAs

// ---------------- device scratch ----------------
__device__ float    g_sq[N_ROWS];
__device__ unsigned g_ap[N_ROWS];          // max intra-class dist^2 (bits)
__device__ unsigned g_an[N_ROWS];          // min inter-class dist^2 (bits)
__device__ float    g_cp[N_ROWS];
__device__ float    g_cn[N_ROWS];
__device__ float    g_csum[NUM_CL * D_DIM];
__device__ int      g_ccnt[NUM_CL];
__device__ float    g_tot[D_DIM];
__device__ float    g_cc;
__device__ int      g_done;                // arrival counter (finalizer resets)
__device__ __align__(16) __nv_bfloat16 g_xb[N_ROWS * D_DIM];

// ---------------- helpers ----------------
__device__ __forceinline__ uint32_t smem_u32(const void* p) {
    uint32_t a;
    asm("{ .reg .u64 t; cvta.to.shared.u64 t, %1; cvt.u32.u64 %0, t; }" : "=r"(a) : "l"(p));
    return a;
}
__device__ __forceinline__ float blockReduceSum(float v, float* sh) {
    int tid = threadIdx.x;
    #pragma unroll
    for (int o = 16; o; o >>= 1) v += __shfl_down_sync(0xffffffffu, v, o);
    __syncthreads();
    if ((tid & 31) == 0) sh[tid >> 5] = v;
    __syncthreads();
    int nw = (blockDim.x + 31) >> 5;
    if (tid < 32) {
        v = (tid < nw) ? sh[tid] : 0.f;
        #pragma unroll
        for (int o = 16; o; o >>= 1) v += __shfl_down_sync(0xffffffffu, v, o);
    }
    return v;
}
__device__ __forceinline__ float warpReduceSum(float v) {
    #pragma unroll
    for (int o = 16; o; o >>= 1) v += __shfl_down_sync(0xffffffffu, v, o);
    return v;
}

// Final scalar reduction, executed inline by the LAST arriving CTA
// (threadFenceReduction pattern). Requires a full 256-thread block.
__device__ void final_reduce(float* __restrict__ out, float* sh) {
    __threadfence();   // acquire side of the arrival handshake
    float s1 = 0.f, s2 = 0.f;
    for (int i = threadIdx.x; i < N_ROWS; i += 256) {
        float ap = sqrtf(__uint_as_float(g_ap[i]));
        float an = sqrtf(__uint_as_float(g_an[i]));
        s1 += fmaxf(ap - an + MARGIN, 0.f);
        s2 += fmaxf(g_cp[i] - g_cn[i] + MARGIN, 0.f);
    }
    s1 = blockReduceSum(s1, sh);
    __syncthreads();
    s2 = blockReduceSum(s2, sh);
    if (threadIdx.x == 0) {
        out[0] = s1 / (float)N_ROWS;
        out[1] = s2 / (float)N_ROWS;
        out[2] = -g_cc / (float)N_ROWS;
    }
}

// Arrival: returns true in ALL threads of the last-arriving CTA.
__device__ __forceinline__ bool arrive_last(int* isLastSh) {
    __syncthreads();                   // all block work done
    if (threadIdx.x == 0) {
        __threadfence();               // release this CTA's global writes
        int old = atomicAdd(&g_done, 1);
        int last = (old == ARRIVALS - 1);
        if (last) g_done = 0;          // reset for next call / graph replay
        *isLastSh = last;
    }
    __syncthreads();
    return *isLastSh != 0;
}

// ---------------- prep: init + fp32->bf16 + squared norms (chain A) -------
__global__ void prep_kernel(const float* __restrict__ X) {
    __shared__ float sh[4];
    int r = blockIdx.x, t = threadIdx.x;   // 128 threads
    const float4 v = *(const float4*)&X[(size_t)r * D_DIM + t * 4];
    __nv_bfloat162 lo = __floats2bfloat162_rn(v.x, v.y);
    __nv_bfloat162 hi = __floats2bfloat162_rn(v.z, v.w);
    *(__nv_bfloat162*)&g_xb[(size_t)r * D_DIM + t * 4]     = lo;
    *(__nv_bfloat162*)&g_xb[(size_t)r * D_DIM + t * 4 + 2] = hi;
    float a = v.x * v.x + v.y * v.y + v.z * v.z + v.w * v.w;
    a = blockReduceSum(a, sh);
    if (t == 0) {
        g_sq[r] = a;
        g_ap[r] = 0u;
        g_an[r] = 0x7f800000u;
    }
}

// one block per class: bitmask membership scan (chain B head)
__global__ void __launch_bounds__(256)
classsum_kernel(const float* __restrict__ X, const int* __restrict__ T) {
    __shared__ unsigned mask[N_ROWS / 32];   // 128 words
    const int c = blockIdx.x, tid = threadIdx.x;

    if (c == 0 && tid == 0) g_cc = 0.f;      // cc accumulator init (chain B owns it)
    if (tid < N_ROWS / 32) mask[tid] = 0u;
    __syncthreads();
    {
        unsigned bits = 0u;
        const int r0 = tid * 16;
        #pragma unroll
        for (int i = 0; i < 16; i++)
            bits |= (T[r0 + i] == c) ? (1u << ((r0 + i) & 31)) : 0u;
        if (bits) atomicOr(&mask[r0 >> 5], bits);
    }
    __syncthreads();

    float a0 = 0.f, a1 = 0.f;
    int cnt = 0;
    #pragma unroll 4
    for (int w = 0; w < N_ROWS / 32; w++) {
        unsigned m = mask[w];
        while (m) {
            int b = __ffs(m) - 1;
            m &= m - 1;
            int r = w * 32 + b;
            cnt++;
            a0 += X[(size_t)r * D_DIM + tid];
            a1 += X[(size_t)r * D_DIM + tid + 256];
        }
    }
    g_csum[c * D_DIM + tid]       = a0;
    g_csum[c * D_DIM + tid + 256] = a1;
    if (tid == 0) g_ccnt[c] = cnt;
}

__global__ void tot_kernel() {   // grid 512, block 128
    __shared__ float sh[4];
    int d = blockIdx.x;
    float s = 0.f;
    for (int c = threadIdx.x; c < NUM_CL; c += 128) s += g_csum[c * D_DIM + d];
    s = blockReduceSum(s, sh);
    if (threadIdx.x == 0) g_tot[d] = s;
}

// ---------------- tensor-core (mma.sync) distance kernel ----------------
#define KC 64
#define STAGES (D_DIM / KC)      // 8
#define NSTG 3
#define STG_BYTES (128 * KC * 2) // 16384 per matrix per stage
#define NTILE 32                 // 4096/128

__device__ __forceinline__ void ldmx4(uint32_t& r0, uint32_t& r1, uint32_t& r2, uint32_t& r3,
                                      uint32_t addr) {
    asm volatile("ldmatrix.sync.aligned.m8n8.x4.shared.b16 {%0,%1,%2,%3}, [%4];"
                 : "=r"(r0), "=r"(r1), "=r"(r2), "=r"(r3) : "r"(addr));
}
__device__ __forceinline__ void mma_bf16(float* c, uint32_t a0, uint32_t a1, uint32_t a2,
                                         uint32_t a3, uint32_t b0, uint32_t b1) {
    asm volatile("mma.sync.aligned.m16n8k16.row.col.f32.bf16.bf16.f32 "
                 "{%0,%1,%2,%3}, {%4,%5,%6,%7}, {%8,%9}, {%0,%1,%2,%3};"
                 : "+f"(c[0]), "+f"(c[1]), "+f"(c[2]), "+f"(c[3])
                 : "r"(a0), "r"(a1), "r"(a2), "r"(a3), "r"(b0), "r"(b1));
}
#define CP16(dst, src) \
    asm volatile("cp.async.cg.shared.global [%0], [%1], 16;" :: "r"(dst), "l"(src))
#define CP_COMMIT() asm volatile("cp.async.commit_group;" ::: "memory")

__global__ void __launch_bounds__(256, 2)
dist_mma_kernel(const int* __restrict__ T, float* __restrict__ out) {
    extern __shared__ __align__(1024) unsigned char dsm[];   // NSTG*2*16KB = 96KB
    __shared__ float sqRs[128], sqCs[128];
    __shared__ int   tRs[128], tCs[128];
    __shared__ unsigned apS[128], anS[128], apSc[128], anSc[128];
    __shared__ int   isLastS;
    __shared__ float fsh[8];

    // ---- pre-PDL-wait setup: no global reads of prep outputs here ----
    const int t = blockIdx.x;
    int by = (int)((2.f * NTILE + 1.f - sqrtf((2.f * NTILE + 1.f) * (2.f * NTILE + 1.f)
                                              - 8.f * (float)t)) * 0.5f);
    while (by > 0 && (by * NTILE - (by * (by - 1)) / 2) > t) by--;
    while (((by + 1) * NTILE - ((by + 1) * by) / 2) <= t) by++;
    const int bx = by + (t - (by * NTILE - (by * (by - 1)) / 2));

    const int tid = threadIdx.x, wid = tid >> 5, lane = tid & 31;
    const int rowBase = by * 128;
    const int colBase = bx * 128;
    const int warpM = (wid >> 2) * 64;
    const int warpN = (wid & 3) * 32;

    if (tid < 128) {
        apS[tid] = 0u;  anS[tid] = 0x7f800000u;
        apSc[tid] = 0u; anSc[tid] = 0x7f800000u;
    }

    const uint32_t sbA = smem_u32(dsm);
    const uint32_t sbB = sbA + NSTG * STG_BYTES;
    const char* Xb = (const char*)g_xb;

    // loader bases: chunk it adds +4096 smem / +32768 gmem (constant strides)
    const int lr = tid >> 3, lu = tid & 7;
    const uint32_t so0 = (uint32_t)(lr * 128 + ((lu * 16) ^ ((lr & 7) << 4)));
    const char* gA0 = Xb + ((size_t)(rowBase + lr) * D_DIM + lu * 8) * 2;
    const char* gB0 = Xb + ((size_t)(colBase + lr) * D_DIM + lu * 8) * 2;

    const int aRow  = warpM + (lane & 15);
    const int aKH   = (lane >> 4) * 16;
    const uint32_t aXor = ((unsigned)(aRow & 7)) << 4;
    const int nRow  = warpN + (lane & 7) + ((lane >> 4) << 3);
    const int bKH   = ((lane >> 3) & 1) * 16;
    const uint32_t bXor = ((unsigned)(nRow & 7)) << 4;

    float acc[4][4][4];
    #pragma unroll
    for (int i = 0; i < 4; i++)
        #pragma unroll
        for (int j = 0; j < 4; j++)
            #pragma unroll
            for (int c = 0; c < 4; c++) acc[i][j][c] = 0.f;

    // ---- PDL: wait for prep's writes to be visible ----
    asm volatile("griddepcontrol.wait;" ::: "memory");

    if (tid < 128) {
        sqRs[tid] = g_sq[rowBase + tid];
        sqCs[tid] = g_sq[colBase + tid];
        tRs[tid]  = T[rowBase + tid];
        tCs[tid]  = T[colBase + tid];
    }

    #define ISSUE_STAGE(s_) do { \
        const uint32_t bo_ = (uint32_t)(((s_) % NSTG) * STG_BYTES) + so0; \
        const size_t ko_ = (size_t)(s_) * (KC * 2); \
        CP16(sbA + bo_,          gA0 + ko_); \
        CP16(sbA + bo_ + 4096,   gA0 + ko_ + 32768); \
        CP16(sbA + bo_ + 8192,   gA0 + ko_ + 65536); \
        CP16(sbA + bo_ + 12288,  gA0 + ko_ + 98304); \
        CP16(sbB + bo_,          gB0 + ko_); \
        CP16(sbB + bo_ + 4096,   gB0 + ko_ + 32768); \
        CP16(sbB + bo_ + 8192,   gB0 + ko_ + 65536); \
        CP16(sbB + bo_ + 12288,  gB0 + ko_ + 98304); \
        CP_COMMIT(); \
    } while (0)

    ISSUE_STAGE(0);
    ISSUE_STAGE(1);

    #pragma unroll
    for (int s = 0; s < STAGES; s++) {
        if (s < STAGES - 1) asm volatile("cp.async.wait_group 1;" ::: "memory");
        else                asm volatile("cp.async.wait_group 0;" ::: "memory");
        __syncthreads();
        if (s + 2 < STAGES) ISSUE_STAGE(s + 2);

        const uint32_t bufOff = (uint32_t)((s % NSTG) * STG_BYTES);
        #pragma unroll
        for (int ks = 0; ks < 4; ks++) {
            uint32_t b[4][2];
            #pragma unroll
            for (int nb = 0; nb < 2; nb++) {
                uint32_t addr = sbB + bufOff + (uint32_t)((nRow + nb * 16) * 128)
                              + (uint32_t)((ks * 32 + bKH) ^ bXor);
                uint32_t q0, q1, q2, q3;
                ldmx4(q0, q1, q2, q3, addr);
                b[nb * 2][0] = q0; b[nb * 2][1] = q1;
                b[nb * 2 + 1][0] = q2; b[nb * 2 + 1][1] = q3;
            }
            #pragma unroll
            for (int mi = 0; mi < 4; mi++) {
                uint32_t addr = sbA + bufOff + (uint32_t)((aRow + mi * 16) * 128)
                              + (uint32_t)((ks * 32 + aKH) ^ aXor);
                uint32_t a0, a1, a2, a3;
                ldmx4(a0, a1, a2, a3, addr);
                #pragma unroll
                for (int nj = 0; nj < 4; nj++)
                    mma_bf16(acc[mi][nj], a0, a1, a2, a3, b[nj][0], b[nj][1]);
            }
        }
    }

    // ---- epilogue ----
    const int g = lane >> 2, q = lane & 3;
    const float INF = __int_as_float(0x7f800000);

    #pragma unroll
    for (int mi = 0; mi < 4; mi++) {
        #pragma unroll
        for (int half = 0; half < 2; half++) {
            const int row = warpM + mi * 16 + g + half * 8;
            const float sqi = sqRs[row];
            const int   ti  = tRs[row];
            float ap = 0.f, an = INF;
            #pragma unroll
            for (int nj = 0; nj < 4; nj++) {
                #pragma unroll
                for (int c = 0; c < 2; c++) {
                    const int col = warpN + nj * 8 + q * 2 + c;
                    float d2 = fmaxf(sqi + sqCs[col] - 2.f * acc[mi][nj][half * 2 + c], 1e-12f);
                    acc[mi][nj][half * 2 + c] = d2;
                    if (ti == tCs[col]) ap = fmaxf(ap, d2);
                    else                an = fminf(an, d2);
                }
            }
            ap = fmaxf(ap, __shfl_xor_sync(0xffffffffu, ap, 1));
            ap = fmaxf(ap, __shfl_xor_sync(0xffffffffu, ap, 2));
            an = fminf(an, __shfl_xor_sync(0xffffffffu, an, 1));
            an = fminf(an, __shfl_xor_sync(0xffffffffu, an, 2));
            if (q == 0) {
                atomicMax(&apS[row], __float_as_uint(ap));
                atomicMin(&anS[row], __float_as_uint(an));
            }
        }
    }
    if (bx != by) {   // diagonal tiles: column pass duplicates row pass
        #pragma unroll
        for (int nj = 0; nj < 4; nj++) {
            #pragma unroll
            for (int c = 0; c < 2; c++) {
                const int col = warpN + nj * 8 + q * 2 + c;
                const int tc = tCs[col];
                float ap = 0.f, an = INF;
                #pragma unroll
                for (int mi = 0; mi < 4; mi++) {
                    #pragma unroll
                    for (int half = 0; half < 2; half++) {
                        const int row = warpM + mi * 16 + g + half * 8;
                        float d2 = acc[mi][nj][half * 2 + c];
                        if (tRs[row] == tc) ap = fmaxf(ap, d2);
                        else                an = fminf(an, d2);
                    }
                }
                ap = fmaxf(ap, __shfl_xor_sync(0xffffffffu, ap, 4));
                ap = fmaxf(ap, __shfl_xor_sync(0xffffffffu, ap, 8));
                ap = fmaxf(ap, __shfl_xor_sync(0xffffffffu, ap, 16));
                an = fminf(an, __shfl_xor_sync(0xffffffffu, an, 4));
                an = fminf(an, __shfl_xor_sync(0xffffffffu, an, 8));
                an = fminf(an, __shfl_xor_sync(0xffffffffu, an, 16));
                if (g == 0) {
                    atomicMax(&apSc[col], __float_as_uint(ap));
                    atomicMin(&anSc[col], __float_as_uint(an));
                }
            }
        }
    }
    __syncthreads();
    if (tid < 128) {
        atomicMax(&g_ap[rowBase + tid], apS[tid]);
        atomicMin(&g_an[rowBase + tid], anS[tid]);
        if (bx != by) {
            atomicMax(&g_ap[colBase + tid], apSc[tid]);
            atomicMin(&g_an[colBase + tid], anSc[tid]);
        }
    }

    // ---- arrival + (maybe) inline final reduction ----
    if (arrive_last(&isLastS)) final_reduce(out, fsh);
}

// ---------------- centroid (+ fused cc): warp per row ----------------
__global__ void __launch_bounds__(256)
centroid_kernel(const float* __restrict__ X, const int* __restrict__ T,
                float* __restrict__ out) {
    __shared__ int   isLastS;
    __shared__ float fsh[8];
    const int warp = threadIdx.x >> 5, lane = threadIdx.x & 31;
    const int i = blockIdx.x * 8 + warp;           // row; grid = 512
    const int c = T[i];
    const float cnt  = (float)g_ccnt[c];
    const float inv1 = 1.f / cnt;
    const float inv2 = 1.f / ((float)N_ROWS - cnt);

    float a1 = 0.f, a2 = 0.f;
    #pragma unroll
    for (int it = 0; it < 4; it++) {
        const int d = (lane + it * 32) * 4;
        const float4 cs = *(const float4*)&g_csum[c * D_DIM + d];
        const float4 x  = *(const float4*)&X[(size_t)i * D_DIM + d];
        const float4 tt = *(const float4*)&g_tot[d];
        float icx = cs.x * inv1 - x.x, icy = cs.y * inv1 - x.y;
        float icz = cs.z * inv1 - x.z, icw = cs.w * inv1 - x.w;
        a1 += icx * icx + icy * icy + icz * icz + icw * icw;
        float ocx = (tt.x - cs.x) * inv2 - x.x, ocy = (tt.y - cs.y) * inv2 - x.y;
        float ocz = (tt.z - cs.z) * inv2 - x.z, ocw = (tt.w - cs.w) * inv2 - x.w;
        a2 += ocx * ocx + ocy * ocy + ocz * ocz + ocw * ocw;
    }
    a1 = warpReduceSum(a1);
    a2 = warpReduceSum(a2);
    if (lane == 0) { g_cp[i] = sqrtf(a1); g_cn[i] = sqrtf(a2); }

    // fused cc: warps owning rows 0..NUM_CL-1 also handle class = row index
    if (i < NUM_CL) {
        const int cnt2 = g_ccnt[i];
        if (cnt2 > 0) {
            const float fc = (float)cnt2;
            const float j1 = 1.f / fc;
            const float j2 = 1.f / ((float)N_ROWS - fc);
            float a = 0.f;
            #pragma unroll
            for (int it = 0; it < 4; it++) {
                const int d = (lane + it * 32) * 4;
                const float4 cs = *(const float4*)&g_csum[i * D_DIM + d];
                const float4 tt = *(const float4*)&g_tot[d];
                float dx = cs.x * j1 - (tt.x - cs.x) * j2;
                float dy = cs.y * j1 - (tt.y - cs.y) * j2;
                float dz = cs.z * j1 - (tt.z - cs.z) * j2;
                float dw = cs.w * j1 - (tt.w - cs.w) * j2;
                a += dx * dx + dy * dy + dz * dz + dw * dw;
            }
            a = warpReduceSum(a);
            if (lane == 0) atomicAdd(&g_cc, fc * sqrtf(a));
        }
    }

    // ---- arrival + (maybe) inline final reduction ----
    if (arrive_last(&isLastS)) final_reduce(out, fsh);
}

// ---------------- entry ----------------
extern "C" void kernel_launch(void* const* d_in, const int* in_sizes, int n_in,
                              void* d_out, int out_size) {
    const float* X = (const float*)d_in[0];
    const int*   T = (const int*)d_in[1];
    float* out = (float*)d_out;

    cudaFuncSetAttribute(dist_mma_kernel,
                         cudaFuncAttributeMaxDynamicSharedMemorySize,
                         NSTG * 2 * STG_BYTES);

    cudaStream_t s2;
    cudaStreamCreateWithFlags(&s2, cudaStreamNonBlocking);
    cudaEvent_t eFork, eJoin;
    cudaEventCreateWithFlags(&eFork, cudaEventDisableTiming);
    cudaEventCreateWithFlags(&eJoin, cudaEventDisableTiming);

    // fork
    cudaEventRecord(eFork, 0);
    cudaStreamWaitEvent(s2, eFork, 0);

    // chain A head (origin stream)
    prep_kernel<<<N_ROWS, 128>>>(X);                       // issue 0

    // chain B (side stream)
    classsum_kernel<<<NUM_CL, 256, 0, s2>>>(X, T);         // issue 1
    tot_kernel<<<D_DIM, 128, 0, s2>>>();                   // issue 2

    // dist at issue index 3. PDL w.r.t. prep (same stream).
    {
        cudaLaunchConfig_t cfg = {};
        cfg.gridDim = dim3((unsigned)(NTILE * (NTILE + 1) / 2), 1, 1);  // 528
        cfg.blockDim = dim3(256, 1, 1);
        cfg.dynamicSmemBytes = NSTG * 2 * STG_BYTES;
        cfg.stream = 0;
        cudaLaunchAttribute attrs[1];
        attrs[0].id = cudaLaunchAttributeProgrammaticStreamSerialization;
        attrs[0].val.programmaticStreamSerializationAllowed = 1;
        cfg.attrs = attrs;
        cfg.numAttrs = 1;
        void* args[] = {(void*)&T, (void*)&out};
        cudaLaunchKernelExC(&cfg, (void*)dist_mma_kernel, args);  // issue 3
    }

    // chain B tail (also a potential finalizer)
    centroid_kernel<<<N_ROWS / 8, 256, 0, s2>>>(X, T, out);       // issue 4

    // join side stream back into origin (capture legality; no work after it)
    cudaEventRecord(eJoin, s2);
    cudaStreamWaitEvent(0, eJoin, 0);
}